// round 14
// baseline (speedup 1.0000x reference)
#include <cuda_runtime.h>
#include <cuda_fp16.h>
#include <math.h>
#include <stdint.h>

#define NN 100000
#define EE 1600000
#define HH 128
#define CC 16

// ---------------- scratch (device globals; no runtime allocation) ----------
__device__ __half g_h16[NN * HH];    // ping buffer
__device__ __half g_agg16[NN * HH];  // pong buffer
__device__ float g_dinv[NN];
__device__ int   g_deg[NN];
__device__ int   g_fill[NN];
__device__ int   g_rowptr[NN];
__device__ int   g_colidx[EE];
__device__ int   g_bsum[256];
__device__ int   g_boff[256];
__device__ uint32_t g_Bpk[3 * HH * HH];  // W^T packed: fp16 hi | fp16 lo << 16, per layer

#define NBLK 196           // ceil(NN/512)
#define PREPW_BLOCKS 24

// ---------------- CSR build -------------------------------------------------
__global__ void k_zero() {
    int i = blockIdx.x * blockDim.x + threadIdx.x;
    if (i < NN) { g_deg[i] = 0; g_fill[i] = 0; }
}

__global__ void k_count(const int* __restrict__ ei) {
    int t = blockIdx.x * blockDim.x + threadIdx.x;
    if (t < EE / 4) {
        int4 d = ((const int4*)(ei + EE))[t];
        atomicAdd(&g_deg[d.x], 1);
        atomicAdd(&g_deg[d.y], 1);
        atomicAdd(&g_deg[d.z], 1);
        atomicAdd(&g_deg[d.w], 1);
    }
}

__device__ __forceinline__ int warp_incl_scan(int v, int lane) {
#pragma unroll
    for (int o = 1; o < 32; o <<= 1) {
        int n = __shfl_up_sync(0xffffffffu, v, o);
        if (lane >= o) v += n;
    }
    return v;
}

// Blocks [0,196): block-local scan of deg -> rowptr, block sums, dinv.
// Blocks [196,220): transpose + fp16 hi/lo split-pack of W1,W2,W3.
__global__ void k_scan1(const float* __restrict__ W1, const float* __restrict__ W2,
                        const float* __restrict__ W3) {
    if (blockIdx.x >= NBLK) {
        int flat = (blockIdx.x - NBLK) * 512 + threadIdx.x;
        for (int t = flat; t < 3 * HH * HH; t += PREPW_BLOCKS * 512) {
            int layer = t >> 14;
            int r = t & (HH * HH - 1);
            const float* W = (layer == 0) ? W1 : ((layer == 1) ? W2 : W3);
            int n = r >> 7, k = r & 127;
            float w = W[k * HH + n];           // W^T
            __half h = __float2half_rn(w);
            float lo = w - __half2float(h);
            __half l = __float2half_rn(lo);
            g_Bpk[t] = (uint32_t)(*(unsigned short*)&h) |
                       ((uint32_t)(*(unsigned short*)&l) << 16);
        }
        return;
    }
    int i = blockIdx.x * 512 + threadIdx.x;
    int lane = threadIdx.x & 31, wid = threadIdx.x >> 5;
    int v = (i < NN) ? g_deg[i] : 0;
    if (i < NN) g_dinv[i] = rsqrtf((float)(v + 1));
    int incl = warp_incl_scan(v, lane);
    __shared__ int ws[16];
    if (lane == 31) ws[wid] = incl;
    __syncthreads();
    if (threadIdx.x < 16) {
        int t = ws[threadIdx.x];
#pragma unroll
        for (int o = 1; o < 16; o <<= 1) {
            int n = __shfl_up_sync(0x0000ffffu, t, o);
            if (threadIdx.x >= (unsigned)o) t += n;
        }
        ws[threadIdx.x] = t;
    }
    __syncthreads();
    int excl = (wid ? ws[wid - 1] : 0) + incl - v;
    if (i < NN) g_rowptr[i] = excl;
    if (threadIdx.x == 0) g_bsum[blockIdx.x] = ws[15];
}

__global__ void k_scan2(int nblk) {
    int lane = threadIdx.x & 31, wid = threadIdx.x >> 5;
    int v = (threadIdx.x < nblk) ? g_bsum[threadIdx.x] : 0;
    int incl = warp_incl_scan(v, lane);
    __shared__ int ws[8];
    if (lane == 31) ws[wid] = incl;
    __syncthreads();
    if (threadIdx.x < 8) {
        int t = ws[threadIdx.x];
#pragma unroll
        for (int o = 1; o < 8; o <<= 1) {
            int n = __shfl_up_sync(0x000000ffu, t, o);
            if (threadIdx.x >= (unsigned)o) t += n;
        }
        ws[threadIdx.x] = t;
    }
    __syncthreads();
    int excl = (wid ? ws[wid - 1] : 0) + incl - v;
    if (threadIdx.x < nblk) g_boff[threadIdx.x] = excl;
}

__global__ void k_fill(const int* __restrict__ ei) {
    int t = blockIdx.x * blockDim.x + threadIdx.x;
    if (t < EE / 4) {
        int4 s = ((const int4*)ei)[t];
        int4 d = ((const int4*)(ei + EE))[t];
        int p0 = g_rowptr[d.x] + g_boff[d.x >> 9] + atomicAdd(&g_fill[d.x], 1);
        g_colidx[p0] = s.x;
        int p1 = g_rowptr[d.y] + g_boff[d.y >> 9] + atomicAdd(&g_fill[d.y], 1);
        g_colidx[p1] = s.y;
        int p2 = g_rowptr[d.z] + g_boff[d.z >> 9] + atomicAdd(&g_fill[d.z], 1);
        g_colidx[p2] = s.z;
        int p3 = g_rowptr[d.w] + g_boff[d.w >> 9] + atomicAdd(&g_fill[d.w], 1);
        g_colidx[p3] = s.w;
    }
}

// ---------------- mma.sync / ldmatrix helpers --------------------------------
__device__ __forceinline__ void mma16816(float* c, const uint32_t* a, const uint32_t* b) {
    asm volatile(
        "mma.sync.aligned.m16n8k16.row.col.f32.f16.f16.f32 "
        "{%0,%1,%2,%3}, {%4,%5,%6,%7}, {%8,%9}, {%0,%1,%2,%3};"
        : "+f"(c[0]), "+f"(c[1]), "+f"(c[2]), "+f"(c[3])
        : "r"(a[0]), "r"(a[1]), "r"(a[2]), "r"(a[3]), "r"(b[0]), "r"(b[1]));
}

__device__ __forceinline__ void ldsm4(uint32_t* r, uint32_t addr) {
    asm volatile("ldmatrix.sync.aligned.m8n8.x4.shared.b16 {%0,%1,%2,%3}, [%4];"
                 : "=r"(r[0]), "=r"(r[1]), "=r"(r[2]), "=r"(r[3]) : "r"(addr));
}

__device__ __forceinline__ uint32_t pack_f16(float x, float y) {
    __half hx = __float2half_rn(x);
    __half hy = __float2half_rn(y);
    return (uint32_t)(*(unsigned short*)&hx) | ((uint32_t)(*(unsigned short*)&hy) << 16);
}

// ---------------- Aggregation core (half-warp per node) ----------------------
__device__ __forceinline__ void add8(float* a, uint4 v) {
    float2 t0 = __half22float2(*(__half2*)&v.x);
    float2 t1 = __half22float2(*(__half2*)&v.y);
    float2 t2 = __half22float2(*(__half2*)&v.z);
    float2 t3 = __half22float2(*(__half2*)&v.w);
    a[0] += t0.x; a[1] += t0.y; a[2] += t1.x; a[3] += t1.y;
    a[4] += t2.x; a[5] += t2.y; a[6] += t3.x; a[7] += t3.y;
}

__device__ __forceinline__ void agg_core(const __half* __restrict__ src, int gw, int lane16,
                                         const float* __restrict__ b, float* o) {
    const uint4* __restrict__ h4 = (const uint4*)src;
    float acc[8] = {0.f, 0.f, 0.f, 0.f, 0.f, 0.f, 0.f, 0.f};
    add8(acc, h4[(size_t)gw * 16 + lane16]);   // self-loop (prescaled row)

    int j = g_rowptr[gw] + g_boff[gw >> 9];
    int e = (gw == NN - 1) ? EE : (g_rowptr[gw + 1] + g_boff[(gw + 1) >> 9]);
    for (; j + 3 < e; j += 4) {
        int s0 = g_colidx[j];
        int s1 = g_colidx[j + 1];
        int s2 = g_colidx[j + 2];
        int s3 = g_colidx[j + 3];
        uint4 v0 = h4[(size_t)s0 * 16 + lane16];
        uint4 v1 = h4[(size_t)s1 * 16 + lane16];
        uint4 v2 = h4[(size_t)s2 * 16 + lane16];
        uint4 v3 = h4[(size_t)s3 * 16 + lane16];
        add8(acc, v0); add8(acc, v1); add8(acc, v2); add8(acc, v3);
    }
    for (; j < e; j++) {
        int s = g_colidx[j];
        add8(acc, h4[(size_t)s * 16 + lane16]);
    }

    float di = g_dinv[gw];
    float4 b0 = ((const float4*)b)[lane16 * 2];
    float4 b1 = ((const float4*)b)[lane16 * 2 + 1];
    o[0] = di * acc[0] + b0.x; o[1] = di * acc[1] + b0.y;
    o[2] = di * acc[2] + b0.z; o[3] = di * acc[3] + b0.w;
    o[4] = di * acc[4] + b1.x; o[5] = di * acc[5] + b1.y;
    o[6] = di * acc[6] + b1.z; o[7] = di * acc[7] + b1.w;
#pragma unroll
    for (int q = 0; q < 8; q++) o[q] = o[q] > 0.f ? o[q] : expm1f(o[q]);
}

// ---------------- Layer-0 GEMM (fp32 A, 3-term split, N-split) ---------------
#define BPAD 136
#define AFPAD 136
#define APAD 72
#define OFF_BH 0
#define OFF_BL 8704
#define OFF_A  17408
#define OFF_AL 26624
#define SM_TOTAL ((OFF_A + 18432) * 2)   // 71680 bytes -> 3 CTAs/SM

__global__ void __launch_bounds__(256, 3) k_gemm_mma(const float* __restrict__ Ain) {
    extern __shared__ __align__(16) unsigned short smu[];
    unsigned short* Bh = smu + OFF_BH;
    unsigned short* Bl = smu + OFF_BL;
    unsigned short* Ah = smu + OFF_A;
    unsigned short* Al = smu + OFF_AL;
    int tid = threadIdx.x;
    int m0 = (blockIdx.x >> 1) * 128;
    int n0 = (blockIdx.x & 1) * 64;
    const uint4* gB4 = (const uint4*)(g_Bpk + n0 * HH);   // layer 0
    uint32_t smbase = (uint32_t)__cvta_generic_to_shared(smu);

    int wid = tid >> 5, lane = tid & 31;
    int wm = wid & 3, wn = wid >> 2;
    int g = lane >> 2, tig = lane & 3;
    int lane7 = lane & 7;
    int aRowOff = lane & 8;
    int aColOff = (lane & 16) ? 8 : 0;
    int bRowOff = (lane & 16) ? 8 : 0;
    int bColOff = lane & 8;

    float acc[2][4][4];
#pragma unroll
    for (int mt = 0; mt < 2; mt++)
#pragma unroll
        for (int nt = 0; nt < 4; nt++)
#pragma unroll
            for (int j = 0; j < 4; j++) acc[mt][nt][j] = 0.f;

    for (int t = tid; t < 64 * 32; t += 256) {
        int n = t >> 5, q = t & 31;
        uint4 v = gB4[t];
        uint2 hh, ll;
        hh.x = __byte_perm(v.x, v.y, 0x5410);
        ll.x = __byte_perm(v.x, v.y, 0x7632);
        hh.y = __byte_perm(v.z, v.w, 0x5410);
        ll.y = __byte_perm(v.z, v.w, 0x7632);
        *(uint2*)&Bh[n * BPAD + q * 4] = hh;
        *(uint2*)&Bl[n * BPAD + q * 4] = ll;
    }
    for (int ch = 0; ch < 2; ch++) {
        if (ch) __syncthreads();
        for (int t = tid; t < 128 * 32; t += 256) {
            int r = t >> 5, c2 = t & 31;
            int gm = m0 + r;
            float2 v = make_float2(0.f, 0.f);
            if (gm < NN) v = *(const float2*)&Ain[(size_t)gm * HH + ch * 64 + c2 * 2];
            uint32_t ph = pack_f16(v.x, v.y);
            float lx = v.x - __half2float(__ushort_as_half((unsigned short)(ph & 0xFFFF)));
            float ly = v.y - __half2float(__ushort_as_half((unsigned short)(ph >> 16)));
            uint32_t pl = pack_f16(lx, ly);
            *(uint32_t*)&Ah[r * APAD + c2 * 2] = ph;
            *(uint32_t*)&Al[r * APAD + c2 * 2] = pl;
        }
        __syncthreads();

#pragma unroll
        for (int kl = 0; kl < 4; kl++) {
            int colA = kl * 16 + aColOff;
            int colB = ch * 64 + kl * 16 + bColOff;
            uint32_t ah[2][4], al[2][4];
#pragma unroll
            for (int mt = 0; mt < 2; mt++) {
                int r = wm * 32 + mt * 16 + lane7 + aRowOff;
                ldsm4(ah[mt], smbase + 2 * (OFF_A + r * APAD + colA));
                ldsm4(al[mt], smbase + 2 * (OFF_AL + r * APAD + colA));
            }
#pragma unroll
            for (int ntp = 0; ntp < 2; ntp++) {
                int n = wn * 32 + ntp * 16 + lane7 + bRowOff;
                uint32_t bh4[4], bl4[4];
                ldsm4(bh4, smbase + 2 * (OFF_BH + n * BPAD + colB));
                ldsm4(bl4, smbase + 2 * (OFF_BL + n * BPAD + colB));
#pragma unroll
                for (int sub = 0; sub < 2; sub++) {
                    int nt = ntp * 2 + sub;
#pragma unroll
                    for (int mt = 0; mt < 2; mt++) {
                        mma16816(acc[mt][nt], ah[mt], &bh4[sub * 2]);
                        mma16816(acc[mt][nt], al[mt], &bh4[sub * 2]);
                        mma16816(acc[mt][nt], ah[mt], &bl4[sub * 2]);
                    }
                }
            }
        }
    }

#pragma unroll
    for (int mt = 0; mt < 2; mt++) {
        int r0 = m0 + wm * 32 + mt * 16 + g;
        int r1 = r0 + 8;
        float d0 = (r0 < NN) ? g_dinv[r0] : 0.f;
        float d1 = (r1 < NN) ? g_dinv[r1] : 0.f;
#pragma unroll
        for (int nt = 0; nt < 4; nt++) {
            int c = n0 + wn * 32 + nt * 8 + tig * 2;
            if (r0 < NN) {
                __half2 o0 = __floats2half2_rn(acc[mt][nt][0] * d0, acc[mt][nt][1] * d0);
                *(__half2*)&g_h16[(size_t)r0 * HH + c] = o0;
            }
            if (r1 < NN) {
                __half2 o1 = __floats2half2_rn(acc[mt][nt][2] * d1, acc[mt][nt][3] * d1);
                *(__half2*)&g_h16[(size_t)r1 * HH + c] = o1;
            }
        }
    }
}

// ---------------- Fused agg + GEMM (layers 1-2) ------------------------------
// Grid 782 (full N=128). srcIsH: 1 -> read g_h16, write g_agg16; 0 -> reverse.
#define F_BH 0
#define F_BL 17408
#define F_A  34816
#define F_TOTAL ((F_A + 17408) * 2)   // 104448 bytes -> 2 CTAs/SM

__global__ void __launch_bounds__(256, 2) k_fused(const float* __restrict__ b,
                                                  int layer, int srcIsH) {
    extern __shared__ __align__(16) unsigned short smu[];
    unsigned short* Bh = smu + F_BH;
    unsigned short* Bl = smu + F_BL;
    const __half* src = srcIsH ? g_h16 : g_agg16;
    __half* dst = srcIsH ? g_agg16 : g_h16;
    int tid = threadIdx.x;
    int m0 = blockIdx.x * 128;
    const uint4* gB4 = (const uint4*)(g_Bpk + layer * HH * HH);
    uint32_t smbase = (uint32_t)__cvta_generic_to_shared(smu);

    // B unpack: 128 rows
    for (int t = tid; t < 128 * 32; t += 256) {
        int n = t >> 5, q = t & 31;
        uint4 v = gB4[t];
        uint2 hh, ll;
        hh.x = __byte_perm(v.x, v.y, 0x5410);
        ll.x = __byte_perm(v.x, v.y, 0x7632);
        hh.y = __byte_perm(v.z, v.w, 0x5410);
        ll.y = __byte_perm(v.z, v.w, 0x7632);
        *(uint2*)&Bh[n * BPAD + q * 4] = hh;
        *(uint2*)&Bl[n * BPAD + q * 4] = ll;
    }

    // Agg phase: build ELU'd A tile in SMEM (fp16), 16 nodes per iteration.
    int nib = tid >> 4, lane16 = tid & 15;
#pragma unroll 1
    for (int it = 0; it < 8; it++) {
        int r = it * 16 + nib;
        int gw = m0 + r;
        float o[8] = {0.f, 0.f, 0.f, 0.f, 0.f, 0.f, 0.f, 0.f};
        if (gw < NN) agg_core(src, gw, lane16, b, o);
        __half2 p0 = __floats2half2_rn(o[0], o[1]);
        __half2 p1 = __floats2half2_rn(o[2], o[3]);
        __half2 p2 = __floats2half2_rn(o[4], o[5]);
        __half2 p3 = __floats2half2_rn(o[6], o[7]);
        uint4 st;
        st.x = *(uint32_t*)&p0; st.y = *(uint32_t*)&p1;
        st.z = *(uint32_t*)&p2; st.w = *(uint32_t*)&p3;
        *(uint4*)&smu[F_A + r * AFPAD + lane16 * 8] = st;
    }
    __syncthreads();

    // MMA phase: warp tile 32x64 (8 warps = 4M x 2N), 2-term split-W.
    int wid = tid >> 5, lane = tid & 31;
    int wm = wid & 3, wn = wid >> 2;
    int g = lane >> 2, tig = lane & 3;
    int lane7 = lane & 7;
    int aRowOff = lane & 8;
    int aColOff = (lane & 16) ? 8 : 0;
    int bRowOff = (lane & 16) ? 8 : 0;
    int bColOff = lane & 8;

    float acc[2][8][4];
#pragma unroll
    for (int mt = 0; mt < 2; mt++)
#pragma unroll
        for (int nt = 0; nt < 8; nt++)
#pragma unroll
            for (int j = 0; j < 4; j++) acc[mt][nt][j] = 0.f;

#pragma unroll
    for (int kl = 0; kl < 8; kl++) {
        int colA = kl * 16 + aColOff;
        int colB = kl * 16 + bColOff;
        uint32_t af[2][4];
#pragma unroll
        for (int mt = 0; mt < 2; mt++) {
            int r = wm * 32 + mt * 16 + lane7 + aRowOff;
            ldsm4(af[mt], smbase + 2 * (F_A + r * AFPAD + colA));
        }
#pragma unroll
        for (int ntp = 0; ntp < 4; ntp++) {
            int n = wn * 64 + ntp * 16 + lane7 + bRowOff;
            uint32_t bh4[4], bl4[4];
            ldsm4(bh4, smbase + 2 * (F_BH + n * BPAD + colB));
            ldsm4(bl4, smbase + 2 * (F_BL + n * BPAD + colB));
#pragma unroll
            for (int sub = 0; sub < 2; sub++) {
                int nt = ntp * 2 + sub;
#pragma unroll
                for (int mt = 0; mt < 2; mt++) {
                    mma16816(acc[mt][nt], af[mt], &bh4[sub * 2]);
                    mma16816(acc[mt][nt], af[mt], &bl4[sub * 2]);
                }
            }
        }
    }

    // Epilogue
#pragma unroll
    for (int mt = 0; mt < 2; mt++) {
        int r0 = m0 + wm * 32 + mt * 16 + g;
        int r1 = r0 + 8;
        float d0 = (r0 < NN) ? g_dinv[r0] : 0.f;
        float d1 = (r1 < NN) ? g_dinv[r1] : 0.f;
#pragma unroll
        for (int nt = 0; nt < 8; nt++) {
            int c = wn * 64 + nt * 8 + tig * 2;
            if (r0 < NN) {
                __half2 o0 = __floats2half2_rn(acc[mt][nt][0] * d0, acc[mt][nt][1] * d0);
                *(__half2*)&dst[(size_t)r0 * HH + c] = o0;
            }
            if (r1 < NN) {
                __half2 o1 = __floats2half2_rn(acc[mt][nt][2] * d1, acc[mt][nt][3] * d1);
                *(__half2*)&dst[(size_t)r1 * HH + c] = o1;
            }
        }
    }
}

// ---------------- Fused layer-3 agg + FC + log_softmax -----------------------
__global__ void __launch_bounds__(256) k_aggfc(const float* __restrict__ b,
                                               const float* __restrict__ Wfc,
                                               const float* __restrict__ bfc,
                                               float* __restrict__ out) {
    __shared__ float WB[16 * 132];
    __shared__ float ps[16][16][CC + 1];
    __shared__ float ls[16][CC + 1];
    for (int t = threadIdx.x; t < HH * CC; t += 256) {
        int k = t >> 4, c = t & 15;
        WB[(k >> 3) * 132 + (k & 7) * 16 + c] = Wfc[t];
    }
    __syncthreads();

    int gw = blockIdx.x * 16 + (threadIdx.x >> 4);
    int lane16 = threadIdx.x & 15;
    int nib = threadIdx.x >> 4;

    float o[8];
    agg_core(g_h16, gw, lane16, b, o);

    float part[CC];
#pragma unroll
    for (int c = 0; c < CC; c++) part[c] = 0.f;
    const float* wb = &WB[lane16 * 132];
#pragma unroll
    for (int q = 0; q < 8; q++) {
        float v = o[q];
        const float4* wr = (const float4*)&wb[q * 16];
        float4 w0 = wr[0], w1 = wr[1], w2 = wr[2], w3 = wr[3];
        part[0] += v * w0.x; part[1] += v * w0.y; part[2] += v * w0.z; part[3] += v * w0.w;
        part[4] += v * w1.x; part[5] += v * w1.y; part[6] += v * w1.z; part[7] += v * w1.w;
        part[8] += v * w2.x; part[9] += v * w2.y; part[10] += v * w2.z; part[11] += v * w2.w;
        part[12] += v * w3.x; part[13] += v * w3.y; part[14] += v * w3.z; part[15] += v * w3.w;
    }
#pragma unroll
    for (int c = 0; c < CC; c++) ps[nib][lane16][c] = part[c];
    __syncthreads();

    int n = threadIdx.x >> 4;
    int c = threadIdx.x & 15;
    float s = bfc[c];
#pragma unroll
    for (int l = 0; l < 16; l++) s += ps[n][l][c];
    ls[n][c] = s;
    __syncthreads();
    float mx = ls[n][0];
#pragma unroll
    for (int cc = 1; cc < CC; cc++) mx = fmaxf(mx, ls[n][cc]);
    float se = 0.f;
#pragma unroll
    for (int cc = 0; cc < CC; cc++) se += expf(ls[n][cc] - mx);
    float lse = mx + logf(se);
    int node = blockIdx.x * 16 + n;
    out[(size_t)node * CC + c] = s - lse;
}

// ---------------- launch ----------------------------------------------------
extern "C" void kernel_launch(void* const* d_in, const int* in_sizes, int n_in,
                              void* d_out, int out_size) {
    const float* x   = (const float*)d_in[0];
    const int*   ei  = (const int*)d_in[1];
    const float* W1  = (const float*)d_in[2];
    const float* b1  = (const float*)d_in[3];
    const float* W2  = (const float*)d_in[4];
    const float* b2  = (const float*)d_in[5];
    const float* W3  = (const float*)d_in[6];
    const float* b3  = (const float*)d_in[7];
    const float* Wfc = (const float*)d_in[8];
    const float* bfc = (const float*)d_in[9];
    float* out = (float*)d_out;

    static int smem_set = 0;
    if (!smem_set) {
        cudaFuncSetAttribute(k_gemm_mma, cudaFuncAttributeMaxDynamicSharedMemorySize, SM_TOTAL);
        cudaFuncSetAttribute(k_fused, cudaFuncAttributeMaxDynamicSharedMemorySize, F_TOTAL);
        smem_set = 1;
    }

    int gemm_grid  = ((NN + 127) / 128) * 2;  // 1564 (layer 0, N-split)
    int fused_grid = (NN + 127) / 128;        // 782

    // Single stream, linear; slot #4 (profiled) is the layer-0 GEMM.
    k_zero<<<(NN + 255) / 256, 256>>>();                          // 1
    k_count<<<(EE / 4 + 255) / 256, 256>>>(ei);                   // 2
    k_scan1<<<NBLK + PREPW_BLOCKS, 512>>>(W1, W2, W3);            // 3 (+dinv, +prepW)
    k_gemm_mma<<<gemm_grid, 256, SM_TOTAL>>>(x);                  // 4 -> g_h16
    k_scan2<<<1, 256>>>(NBLK);                                    // 5
    k_fill<<<(EE / 4 + 255) / 256, 256>>>(ei);                    // 6
    k_fused<<<fused_grid, 256, F_TOTAL>>>(b1, 1, 1);              // 7 agg1+gemm2 -> g_agg16
    k_fused<<<fused_grid, 256, F_TOTAL>>>(b2, 2, 0);              // 8 agg2+gemm3 -> g_h16
    k_aggfc<<<NN / 16, 256>>>(b3, Wfc, bfc, out);                 // 9 agg3+FC -> out
}

// round 15
// speedup vs baseline: 1.2604x; 1.2604x over previous
#include <cuda_runtime.h>
#include <cuda_fp16.h>
#include <math.h>
#include <stdint.h>

#define NN 100000
#define EE 1600000
#define HH 128
#define CC 16

__device__ __half g_h16[NN * HH];
__device__ __half g_agg16[NN * HH];
__device__ float g_dinv[NN];
__device__ int   g_deg[NN];
__device__ int   g_fill[NN];
__device__ int   g_rowptr[NN];
__device__ int   g_colidx[EE];
__device__ int   g_bsum[256];
__device__ int   g_boff[256];
__device__ uint32_t g_Bpk[3 * HH * HH];

#define NBLK 196
#define PREPW_BLOCKS 24

__global__ void k_zero() {
    int i = blockIdx.x * blockDim.x + threadIdx.x;
    if (i < NN) { g_deg[i] = 0; g_fill[i] = 0; }
}

__global__ void k_count(const int* __restrict__ ei) {
    int t = blockIdx.x * blockDim.x + threadIdx.x;
    if (t < EE / 4) {
        int4 d = ((const int4*)(ei + EE))[t];
        atomicAdd(&g_deg[d.x], 1);
        atomicAdd(&g_deg[d.y], 1);
        atomicAdd(&g_deg[d.z], 1);
        atomicAdd(&g_deg[d.w], 1);
    }
}

__device__ __forceinline__ int warp_incl_scan(int v, int lane) {
#pragma unroll
    for (int o = 1; o < 32; o <<= 1) {
        int n = __shfl_up_sync(0xffffffffu, v, o);
        if (lane >= o) v += n;
    }
    return v;
}

__global__ void k_scan1(const float* __restrict__ W1, const float* __restrict__ W2,
                        const float* __restrict__ W3) {
    if (blockIdx.x >= NBLK) {
        int flat = (blockIdx.x - NBLK) * 512 + threadIdx.x;
        for (int t = flat; t < 3 * HH * HH; t += PREPW_BLOCKS * 512) {
            int layer = t >> 14;
            int r = t & (HH * HH - 1);
            const float* W = (layer == 0) ? W1 : ((layer == 1) ? W2 : W3);
            int n = r >> 7, k = r & 127;
            float w = W[k * HH + n];
            __half h = __float2half_rn(w);
            float lo = w - __half2float(h);
            __half l = __float2half_rn(lo);
            g_Bpk[t] = (uint32_t)(*(unsigned short*)&h) |
                       ((uint32_t)(*(unsigned short*)&l) << 16);
        }
        return;
    }
    int i = blockIdx.x * 512 + threadIdx.x;
    int lane = threadIdx.x & 31, wid = threadIdx.x >> 5;
    int v = (i < NN) ? g_deg[i] : 0;
    if (i < NN) g_dinv[i] = rsqrtf((float)(v + 1));
    int incl = warp_incl_scan(v, lane);
    __shared__ int ws[16];
    if (lane == 31) ws[wid] = incl;
    __syncthreads();
    if (threadIdx.x < 16) {
        int t = ws[threadIdx.x];
#pragma unroll
        for (int o = 1; o < 16; o <<= 1) {
            int n = __shfl_up_sync(0x0000ffffu, t, o);
            if (threadIdx.x >= (unsigned)o) t += n;
        }
        ws[threadIdx.x] = t;
    }
    __syncthreads();
    int excl = (wid ? ws[wid - 1] : 0) + incl - v;
    if (i < NN) g_rowptr[i] = excl;
    if (threadIdx.x == 0) g_bsum[blockIdx.x] = ws[15];
}

__global__ void k_scan2(int nblk) {
    int lane = threadIdx.x & 31, wid = threadIdx.x >> 5;
    int v = (threadIdx.x < nblk) ? g_bsum[threadIdx.x] : 0;
    int incl = warp_incl_scan(v, lane);
    __shared__ int ws[8];
    if (lane == 31) ws[wid] = incl;
    __syncthreads();
    if (threadIdx.x < 8) {
        int t = ws[threadIdx.x];
#pragma unroll
        for (int o = 1; o < 8; o <<= 1) {
            int n = __shfl_up_sync(0x000000ffu, t, o);
            if (threadIdx.x >= (unsigned)o) t += n;
        }
        ws[threadIdx.x] = t;
    }
    __syncthreads();
    int excl = (wid ? ws[wid - 1] : 0) + incl - v;
    if (threadIdx.x < nblk) g_boff[threadIdx.x] = excl;
}

__global__ void k_fill(const int* __restrict__ ei) {
    int t = blockIdx.x * blockDim.x + threadIdx.x;
    if (t < EE / 4) {
        int4 s = ((const int4*)ei)[t];
        int4 d = ((const int4*)(ei + EE))[t];
        int p0 = g_rowptr[d.x] + g_boff[d.x >> 9] + atomicAdd(&g_fill[d.x], 1);
        g_colidx[p0] = s.x;
        int p1 = g_rowptr[d.y] + g_boff[d.y >> 9] + atomicAdd(&g_fill[d.y], 1);
        g_colidx[p1] = s.y;
        int p2 = g_rowptr[d.z] + g_boff[d.z >> 9] + atomicAdd(&g_fill[d.z], 1);
        g_colidx[p2] = s.z;
        int p3 = g_rowptr[d.w] + g_boff[d.w >> 9] + atomicAdd(&g_fill[d.w], 1);
        g_colidx[p3] = s.w;
    }
}

__device__ __forceinline__ void mma16816(float* c, const uint32_t* a, const uint32_t* b) {
    asm volatile(
        "mma.sync.aligned.m16n8k16.row.col.f32.f16.f16.f32 "
        "{%0,%1,%2,%3}, {%4,%5,%6,%7}, {%8,%9}, {%0,%1,%2,%3};"
        : "+f"(c[0]), "+f"(c[1]), "+f"(c[2]), "+f"(c[3])
        : "r"(a[0]), "r"(a[1]), "r"(a[2]), "r"(a[3]), "r"(b[0]), "r"(b[1]));
}

__device__ __forceinline__ void ldsm4(uint32_t* r, uint32_t addr) {
    asm volatile("ldmatrix.sync.aligned.m8n8.x4.shared.b16 {%0,%1,%2,%3}, [%4];"
                 : "=r"(r[0]), "=r"(r[1]), "=r"(r[2]), "=r"(r[3]) : "r"(addr));
}

__device__ __forceinline__ uint32_t pack_f16(float x, float y) {
    __half hx = __float2half_rn(x);
    __half hy = __float2half_rn(y);
    return (uint32_t)(*(unsigned short*)&hx) | ((uint32_t)(*(unsigned short*)&hy) << 16);
}

#define BPAD 136
#define AFPAD 136
#define APAD 72
#define OFF_BH 0
#define OFF_BL 8704
#define OFF_A  17408
#define OFF_AL 26624
#define SM_TOTAL ((OFF_A + 18432) * 2)

__global__ void __launch_bounds__(256, 3) k_gemm_mma(const float* __restrict__ Ain,
                                                     int useAgg, int layer) {
    extern __shared__ __align__(16) unsigned short smu[];
    unsigned short* Bh = smu + OFF_BH;
    unsigned short* Bl = smu + OFF_BL;
    int tid = threadIdx.x;
    int m0 = (blockIdx.x >> 1) * 128;
    int n0 = (blockIdx.x & 1) * 64;
    const uint4* gB4 = (const uint4*)(g_Bpk + layer * HH * HH + n0 * HH);
    uint32_t smbase = (uint32_t)__cvta_generic_to_shared(smu);

    int wid = tid >> 5, lane = tid & 31;
    int wm = wid & 3, wn = wid >> 2;
    int g = lane >> 2, tig = lane & 3;
    int lane7 = lane & 7;
    int aRowOff = lane & 8;
    int aColOff = (lane & 16) ? 8 : 0;
    int bRowOff = (lane & 16) ? 8 : 0;
    int bColOff = lane & 8;

    float acc[2][4][4];
#pragma unroll
    for (int mt = 0; mt < 2; mt++)
#pragma unroll
        for (int nt = 0; nt < 4; nt++)
#pragma unroll
            for (int j = 0; j < 4; j++) acc[mt][nt][j] = 0.f;

    if (useAgg) {
        for (int t = tid; t < 128 * 16; t += 256) {
            int r = t >> 4, c8 = t & 15;
            int gm = m0 + r;
            uint32_t dst = smbase + 2 * (OFF_A + r * AFPAD + c8 * 8);
            const void* src = &g_agg16[(size_t)(gm < NN ? gm : 0) * HH + c8 * 8];
            int srcsz = (gm < NN) ? 16 : 0;
            asm volatile("cp.async.cg.shared.global [%0], [%1], 16, %2;"
                         :: "r"(dst), "l"(src), "r"(srcsz));
        }
        for (int t = tid; t < 64 * 32; t += 256) {
            int n = t >> 5, q = t & 31;
            uint4 v = gB4[t];
            uint2 hh, ll;
            hh.x = __byte_perm(v.x, v.y, 0x5410);
            ll.x = __byte_perm(v.x, v.y, 0x7632);
            hh.y = __byte_perm(v.z, v.w, 0x5410);
            ll.y = __byte_perm(v.z, v.w, 0x7632);
            *(uint2*)&Bh[n * BPAD + q * 4] = hh;
            *(uint2*)&Bl[n * BPAD + q * 4] = ll;
        }
        asm volatile("cp.async.commit_group;\ncp.async.wait_group 0;" ::: "memory");
        __syncthreads();

#pragma unroll
        for (int kl = 0; kl < 8; kl++) {
            int colA = kl * 16 + aColOff;
            int colB = kl * 16 + bColOff;
            uint32_t af[2][4];
#pragma unroll
            for (int mt = 0; mt < 2; mt++) {
                int r = wm * 32 + mt * 16 + lane7 + aRowOff;
                ldsm4(af[mt], smbase + 2 * (OFF_A + r * AFPAD + colA));
            }
#pragma unroll
            for (int ntp = 0; ntp < 2; ntp++) {
                int n = wn * 32 + ntp * 16 + lane7 + bRowOff;
                uint32_t bh4[4], bl4[4];
                ldsm4(bh4, smbase + 2 * (OFF_BH + n * BPAD + colB));
                ldsm4(bl4, smbase + 2 * (OFF_BL + n * BPAD + colB));
#pragma unroll
                for (int sub = 0; sub < 2; sub++) {
                    int nt = ntp * 2 + sub;
#pragma unroll
                    for (int mt = 0; mt < 2; mt++) {
                        mma16816(acc[mt][nt], af[mt], &bh4[sub * 2]);
                        mma16816(acc[mt][nt], af[mt], &bl4[sub * 2]);
                    }
                }
            }
        }
    } else {
        unsigned short* Ah = smu + OFF_A;
        unsigned short* Al = smu + OFF_AL;
        for (int t = tid; t < 64 * 32; t += 256) {
            int n = t >> 5, q = t & 31;
            uint4 v = gB4[t];
            uint2 hh, ll;
            hh.x = __byte_perm(v.x, v.y, 0x5410);
            ll.x = __byte_perm(v.x, v.y, 0x7632);
            hh.y = __byte_perm(v.z, v.w, 0x5410);
            ll.y = __byte_perm(v.z, v.w, 0x7632);
            *(uint2*)&Bh[n * BPAD + q * 4] = hh;
            *(uint2*)&Bl[n * BPAD + q * 4] = ll;
        }
        for (int ch = 0; ch < 2; ch++) {
            if (ch) __syncthreads();
            for (int t = tid; t < 128 * 32; t += 256) {
                int r = t >> 5, c2 = t & 31;
                int gm = m0 + r;
                float2 v = make_float2(0.f, 0.f);
                if (gm < NN) v = *(const float2*)&Ain[(size_t)gm * HH + ch * 64 + c2 * 2];
                uint32_t ph = pack_f16(v.x, v.y);
                float lx = v.x - __half2float(__ushort_as_half((unsigned short)(ph & 0xFFFF)));
                float ly = v.y - __half2float(__ushort_as_half((unsigned short)(ph >> 16)));
                uint32_t pl = pack_f16(lx, ly);
                *(uint32_t*)&Ah[r * APAD + c2 * 2] = ph;
                *(uint32_t*)&Al[r * APAD + c2 * 2] = pl;
            }
            __syncthreads();

#pragma unroll
            for (int kl = 0; kl < 4; kl++) {
                int colA = kl * 16 + aColOff;
                int colB = ch * 64 + kl * 16 + bColOff;
                uint32_t ah[2][4], al[2][4];
#pragma unroll
                for (int mt = 0; mt < 2; mt++) {
                    int r = wm * 32 + mt * 16 + lane7 + aRowOff;
                    ldsm4(ah[mt], smbase + 2 * (OFF_A + r * APAD + colA));
                    ldsm4(al[mt], smbase + 2 * (OFF_AL + r * APAD + colA));
                }
#pragma unroll
                for (int ntp = 0; ntp < 2; ntp++) {
                    int n = wn * 32 + ntp * 16 + lane7 + bRowOff;
                    uint32_t bh4[4], bl4[4];
                    ldsm4(bh4, smbase + 2 * (OFF_BH + n * BPAD + colB));
                    ldsm4(bl4, smbase + 2 * (OFF_BL + n * BPAD + colB));
#pragma unroll
                    for (int sub = 0; sub < 2; sub++) {
                        int nt = ntp * 2 + sub;
#pragma unroll
                        for (int mt = 0; mt < 2; mt++) {
                            mma16816(acc[mt][nt], ah[mt], &bh4[sub * 2]);
                            mma16816(acc[mt][nt], al[mt], &bh4[sub * 2]);
                            mma16816(acc[mt][nt], ah[mt], &bl4[sub * 2]);
                        }
                    }
                }
            }
        }
    }

#pragma unroll
    for (int mt = 0; mt < 2; mt++) {
        int r0 = m0 + wm * 32 + mt * 16 + g;
        int r1 = r0 + 8;
        float d0 = (r0 < NN) ? g_dinv[r0] : 0.f;
        float d1 = (r1 < NN) ? g_dinv[r1] : 0.f;
#pragma unroll
        for (int nt = 0; nt < 4; nt++) {
            int c = n0 + wn * 32 + nt * 8 + tig * 2;
            if (r0 < NN) {
                __half2 o0 = __floats2half2_rn(acc[mt][nt][0] * d0, acc[mt][nt][1] * d0);
                *(__half2*)&g_h16[(size_t)r0 * HH + c] = o0;
            }
            if (r1 < NN) {
                __half2 o1 = __floats2half2_rn(acc[mt][nt][2] * d1, acc[mt][nt][3] * d1);
                *(__half2*)&g_h16[(size_t)r1 * HH + c] = o1;
            }
        }
    }
}

__device__ __forceinline__ void add8(float* a, uint4 v) {
    float2 t0 = __half22float2(*(__half2*)&v.x);
    float2 t1 = __half22float2(*(__half2*)&v.y);
    float2 t2 = __half22float2(*(__half2*)&v.z);
    float2 t3 = __half22float2(*(__half2*)&v.w);
    a[0] += t0.x; a[1] += t0.y; a[2] += t1.x; a[3] += t1.y;
    a[4] += t2.x; a[5] += t2.y; a[6] += t3.x; a[7] += t3.y;
}

__device__ __forceinline__ void agg_core(int gw, int lane16, const float* __restrict__ b,
                                         float* o) {
    const uint4* __restrict__ h4 = (const uint4*)g_h16;
    float acc[8] = {0.f, 0.f, 0.f, 0.f, 0.f, 0.f, 0.f, 0.f};
    add8(acc, __ldg(&h4[(size_t)gw * 16 + lane16]));

    int j = g_rowptr[gw] + g_boff[gw >> 9];
    int e = (gw == NN - 1) ? EE : (g_rowptr[gw + 1] + g_boff[(gw + 1) >> 9]);
    for (; j + 3 < e; j += 4) {
        int s0 = g_colidx[j];
        int s1 = g_colidx[j + 1];
        int s2 = g_colidx[j + 2];
        int s3 = g_colidx[j + 3];
        uint4 v0 = __ldg(&h4[(size_t)s0 * 16 + lane16]);
        uint4 v1 = __ldg(&h4[(size_t)s1 * 16 + lane16]);
        uint4 v2 = __ldg(&h4[(size_t)s2 * 16 + lane16]);
        uint4 v3 = __ldg(&h4[(size_t)s3 * 16 + lane16]);
        add8(acc, v0); add8(acc, v1); add8(acc, v2); add8(acc, v3);
    }
    for (; j < e; j++) {
        int s = g_colidx[j];
        add8(acc, __ldg(&h4[(size_t)s * 16 + lane16]));
    }

    float di = g_dinv[gw];
    float4 b0 = ((const float4*)b)[lane16 * 2];
    float4 b1 = ((const float4*)b)[lane16 * 2 + 1];
    o[0] = di * acc[0] + b0.x; o[1] = di * acc[1] + b0.y;
    o[2] = di * acc[2] + b0.z; o[3] = di * acc[3] + b0.w;
    o[4] = di * acc[4] + b1.x; o[5] = di * acc[5] + b1.y;
    o[6] = di * acc[6] + b1.z; o[7] = di * acc[7] + b1.w;
#pragma unroll
    for (int q = 0; q < 8; q++) o[q] = o[q] > 0.f ? o[q] : expm1f(o[q]);
}

__global__ void __launch_bounds__(256) k_agg(const float* __restrict__ b) {
    int gw = (blockIdx.x * 256 + threadIdx.x) >> 4;
    int lane16 = threadIdx.x & 15;
    if (gw >= NN) return;
    float o[8];
    agg_core(gw, lane16, b, o);
    __half2 p0 = __floats2half2_rn(o[0], o[1]);
    __half2 p1 = __floats2half2_rn(o[2], o[3]);
    __half2 p2 = __floats2half2_rn(o[4], o[5]);
    __half2 p3 = __floats2half2_rn(o[6], o[7]);
    uint4 st;
    st.x = *(uint32_t*)&p0; st.y = *(uint32_t*)&p1;
    st.z = *(uint32_t*)&p2; st.w = *(uint32_t*)&p3;
    ((uint4*)g_agg16)[(size_t)gw * 16 + lane16] = st;
}

__global__ void __launch_bounds__(256) k_aggfc(const float* __restrict__ b,
                                               const float* __restrict__ Wfc,
                                               const float* __restrict__ bfc,
                                               float* __restrict__ out) {
    __shared__ float WB[16 * 132];
    __shared__ float ps[16][16][CC + 1];
    __shared__ float ls[16][CC + 1];
    for (int t = threadIdx.x; t < HH * CC; t += 256) {
        int k = t >> 4, c = t & 15;
        WB[(k >> 3) * 132 + (k & 7) * 16 + c] = Wfc[t];
    }
    __syncthreads();

    int gw = blockIdx.x * 16 + (threadIdx.x >> 4);
    int lane16 = threadIdx.x & 15;
    int nib = threadIdx.x >> 4;

    float o[8];
    agg_core(gw, lane16, b, o);

    float part[CC];
#pragma unroll
    for (int c = 0; c < CC; c++) part[c] = 0.f;
    const float* wb = &WB[lane16 * 132];
#pragma unroll
    for (int q = 0; q < 8; q++) {
        float v = o[q];
        const float4* wr = (const float4*)&wb[q * 16];
        float4 w0 = wr[0], w1 = wr[1], w2 = wr[2], w3 = wr[3];
        part[0] += v * w0.x; part[1] += v * w0.y; part[2] += v * w0.z; part[3] += v * w0.w;
        part[4] += v * w1.x; part[5] += v * w1.y; part[6] += v * w1.z; part[7] += v * w1.w;
        part[8] += v * w2.x; part[9] += v * w2.y; part[10] += v * w2.z; part[11] += v * w2.w;
        part[12] += v * w3.x; part[13] += v * w3.y; part[14] += v * w3.z; part[15] += v * w3.w;
    }
#pragma unroll
    for (int c = 0; c < CC; c++) ps[nib][lane16][c] = part[c];
    __syncthreads();

    int n = threadIdx.x >> 4;
    int c = threadIdx.x & 15;
    float s = bfc[c];
#pragma unroll
    for (int l = 0; l < 16; l++) s += ps[n][l][c];
    ls[n][c] = s;
    __syncthreads();
    float mx = ls[n][0];
#pragma unroll
    for (int cc = 1; cc < CC; cc++) mx = fmaxf(mx, ls[n][cc]);
    float se = 0.f;
#pragma unroll
    for (int cc = 0; cc < CC; cc++) se += expf(ls[n][cc] - mx);
    float lse = mx + logf(se);
    int node = blockIdx.x * 16 + n;
    out[(size_t)node * CC + c] = s - lse;
}

extern "C" void kernel_launch(void* const* d_in, const int* in_sizes, int n_in,
                              void* d_out, int out_size) {
    const float* x   = (const float*)d_in[0];
    const int*   ei  = (const int*)d_in[1];
    const float* W1  = (const float*)d_in[2];
    const float* b1  = (const float*)d_in[3];
    const float* W2  = (const float*)d_in[4];
    const float* b2  = (const float*)d_in[5];
    const float* W3  = (const float*)d_in[6];
    const float* b3  = (const float*)d_in[7];
    const float* Wfc = (const float*)d_in[8];
    const float* bfc = (const float*)d_in[9];
    float* out = (float*)d_out;

    static int smem_set = 0;
    if (!smem_set) {
        cudaFuncSetAttribute(k_gemm_mma, cudaFuncAttributeMaxDynamicSharedMemorySize, SM_TOTAL);
        smem_set = 1;
    }

    int gemm_grid = ((NN + 127) / 128) * 2;  // 1564
    int agg_grid  = (NN * 16 + 255) / 256;   // 6250

    k_zero<<<(NN + 255) / 256, 256>>>();                          // 1
    k_count<<<(EE / 4 + 255) / 256, 256>>>(ei);                   // 2
    k_scan1<<<NBLK + PREPW_BLOCKS, 512>>>(W1, W2, W3);            // 3
    k_gemm_mma<<<gemm_grid, 256, SM_TOTAL>>>(x, 0, 0);            // 4 -> g_h16
    k_scan2<<<1, 256>>>(NBLK);                                    // 5
    k_fill<<<(EE / 4 + 255) / 256, 256>>>(ei);                    // 6
    k_agg<<<agg_grid, 256>>>(b1);                                 // 7 g_h16 -> g_agg16

    k_gemm_mma<<<gemm_grid, 256, SM_TOTAL>>>(nullptr, 1, 1);      // 8 g_agg16 -> g_h16
    k_agg<<<agg_grid, 256>>>(b2);                                 // 9 g_h16 -> g_agg16

    k_gemm_mma<<<gemm_grid, 256, SM_TOTAL>>>(nullptr, 1, 2);      // 10 g_agg16 -> g_h16
    k_aggfc<<<NN / 16, 256>>>(b3, Wfc, bfc, out);                 // 11 g_h16 -> out
}